// round 14
// baseline (speedup 1.0000x reference)
#include <cuda_runtime.h>
#include <cuda_bf16.h>
#include <cstdint>
#include <cstddef>

// ============================================================================
// CustomContrastiveLoss via mma.sync fp8(e4m3) + fixed-reference base-2 sum-exp.
//
//   loss = mean_i sum_{j: ad_j==ad_i & valid} min(lse2_i - t_ij, -log2(1e-12))
//   t = (logits*log2e) @ labels^T,  lse2_i = log2 sum_j 2^{t_ij}  (masked)
//
// R12 vs R11 (116.2us; best 113.1):
//  - bf16 mma.sync was at its HMMA-ISSUE floor (rt~16cyc/SMSP, invariant to
//    occupancy — proven by R10/R11 nulls). Switch to fp8 e4m3 m16n8k32:
//    2x MAC/instr -> floor halves (~32us GEMM).
//  - Precision: only lse carries fp8 error (positives' t recomputed exactly
//    in fp32 in k_pairs); ~96% of positive terms sit on the -log2(1e-12) cap
//    (29 log2-unit margin). Predicted rel_err ~1e-4.
//  - NSTRIPE=8 (512 CTAs x 8 tiles), ~90 regs, 50KB smem -> 2-3 CTAs/SM
//    co-resident for cross-SM load balancing.
// ============================================================================

#define NT       8192
#define DD       128
#define TM       128
#define TN       128
#define NSTRIPE  8
#define CSPAN    (NT / NSTRIPE)     // 1024
#define TILES    (CSPAN / TN)       // 8
#define GROWS    16
#define LCAP     2048

#define LOG2E   1.4426950408889634f
#define CAPV    39.863137f
#define M0      64.0f
#define NEG_INF (__int_as_float(0xff800000))

// dynamic smem layout (fp8 tiles: 128 rows x 128 bytes = 16KB)
#define A_OFF    0                  // 16384
#define B_OFF    16384              // 2 bufs x 16384
#define RED_OFF  49152              // 4 x 128 f32 = 2048
#define SMEM_SZ  51200

// device scratch
__device__ uint8_t   g_A8[NT * DD];        // e4m3(logits * log2e)
__device__ uint8_t   g_B8[NT * DD];        // e4m3(labels), masked cols zeroed
__device__ float     g_ps[NSTRIPE * NT];   // per-stripe sum of 2^(t-M0)
__device__ long long g_key[NT];
__device__ float     g_loss;
__device__ unsigned  g_done;

__device__ __forceinline__ float ex2(float x) {
    float y; asm("ex2.approx.f32 %0, %1;" : "=f"(y) : "f"(x)); return y;
}
__device__ __forceinline__ float lg2(float x) {
    float y; asm("lg2.approx.f32 %0, %1;" : "=f"(y) : "f"(x)); return y;
}
__device__ __forceinline__ uint32_t s2u(const void* p) {
    uint32_t a;
    asm("{ .reg .u64 t; cvta.to.shared.u64 t, %1; cvt.u32.u64 %0, t; }" : "=r"(a) : "l"(p));
    return a;
}
__device__ __forceinline__ void cpa16(uint32_t dst, const void* src) {
    asm volatile("cp.async.cg.shared.global [%0], [%1], 16;" :: "r"(dst), "l"(src) : "memory");
}
__device__ __forceinline__ void cp_commit() {
    asm volatile("cp.async.commit_group;" ::: "memory");
}
template<int N> __device__ __forceinline__ void cp_wait() {
    asm volatile("cp.async.wait_group %0;" :: "n"(N) : "memory");
}
__device__ __forceinline__ void ldsm4(uint32_t* r, uint32_t addr) {
    asm volatile("ldmatrix.sync.aligned.m8n8.x4.shared.b16 {%0, %1, %2, %3}, [%4];"
                 : "=r"(r[0]), "=r"(r[1]), "=r"(r[2]), "=r"(r[3]) : "r"(addr));
}
// fp8 e4m3 MMA: D(16x8,f32) += A(16x32) * B(32x8)
__device__ __forceinline__ void mma16832(float* c, const uint32_t* a, const uint32_t* b) {
    asm volatile(
        "mma.sync.aligned.m16n8k32.row.col.f32.e4m3.e4m3.f32 "
        "{%0, %1, %2, %3}, {%4, %5, %6, %7}, {%8, %9}, {%0, %1, %2, %3};"
        : "+f"(c[0]), "+f"(c[1]), "+f"(c[2]), "+f"(c[3])
        : "r"(a[0]), "r"(a[1]), "r"(a[2]), "r"(a[3]), "r"(b[0]), "r"(b[1]));
}
// pack 2 f32 -> 2 e4m3 bytes (x -> low byte, y -> high byte)
__device__ __forceinline__ uint32_t f2e4m3x2(float x, float y) {
    uint16_t p;
    asm("cvt.rn.satfinite.e4m3x2.f32 %0, %1, %2;" : "=h"(p) : "f"(y), "f"(x));
    return (uint32_t)p;
}
// XOR-swizzled byte offset inside a [row][128 fp8] tile: chunk = 16B unit 0..7
__device__ __forceinline__ uint32_t swz(int row, int chunk) {
    return (uint32_t)(row * 128 + (((chunk ^ (row & 7)) & 7) << 4));
}

// ---------------------------------------------------------------------------
// k_prep: blocks 0..1023 convert fp32 -> e4m3 (A scaled by log2e; B cols
//         zeroed where invalid). block 1024 builds keys + zeros accumulators.
// ---------------------------------------------------------------------------
__global__ __launch_bounds__(256)
void k_prep(const float* __restrict__ logits,
            const float* __restrict__ labels,
            const void*  __restrict__ ad,
            const int*   __restrict__ mask) {
    const int tid = threadIdx.x;
    if (blockIdx.x < 1024) {
        int idx = blockIdx.x * 256 + tid;          // float4 index, 262144 total
        float4 a = ((const float4*)logits)[idx];
        float4 b = ((const float4*)labels)[idx];
        float mv = mask[idx >> 5] ? 1.0f : 0.0f;   // 32 float4 per row
        uint32_t ua = f2e4m3x2(a.x * LOG2E, a.y * LOG2E)
                    | (f2e4m3x2(a.z * LOG2E, a.w * LOG2E) << 16);
        uint32_t ub = f2e4m3x2(b.x * mv, b.y * mv)
                    | (f2e4m3x2(b.z * mv, b.w * mv) << 16);
        ((uint32_t*)g_A8)[idx] = ua;
        ((uint32_t*)g_B8)[idx] = ub;
    } else {
        __shared__ int ok;
        if (tid == 0) { ok = 1; g_loss = 0.0f; g_done = 0u; }
        __syncthreads();
        const int* a32 = (const int*)ad;
        int bad = 0;
        for (int i = tid; i < NT / 2; i += 256)    // stays inside 32KB either way
            if (a32[2 * i + 1] != 0) bad = 1;
        if (bad) atomicExch(&ok, 0);
        __syncthreads();
        const int is64 = ok;
        for (int j = tid; j < NT; j += 256) {
            long long v = is64 ? ((const long long*)ad)[j]
                               : (long long)((const int*)ad)[j];
            if (mask[j] == 0) v = (long long)0x8000000000000000ULL + j;
            g_key[j] = v;
        }
    }
}

// ---------------------------------------------------------------------------
// k_lse_mma: 256 threads, warp grid 2(M) x 4(N), warp tile 64x32, fp8 k32.
// mi loop split in 2 halves to keep c at 32 regs (-> 2-3 CTAs/SM).
// Invalid columns are zero in g_B8 -> t=0 -> 2^-64 contribution (negligible).
// ---------------------------------------------------------------------------
__global__ __launch_bounds__(256)
void k_lse_mma() {
    extern __shared__ char sm[];
    const int tid  = threadIdx.x;
    const int lane = tid & 31;
    const int wid  = tid >> 5;
    const int wm   = wid & 1;        // M half (rows 64*wm ..)
    const int wn   = wid >> 1;       // N quarter (cols 32*wn ..)
    const int row0 = blockIdx.x * TM;
    const int colbase = blockIdx.y * CSPAN;
    const uint32_t smb = s2u(sm);

    // A tile (once) + B tile 0, via cp.async: 16KB each = 4 cpa16/thread
    {
        const char* gA = (const char*)g_A8 + (size_t)row0 * 128;
        const char* gB = (const char*)g_B8 + (size_t)colbase * 128;
        #pragma unroll
        for (int it = 0; it < 4; ++it) {
            int g = tid + it * 256;            // chunk id 0..1023
            int r = g >> 3, c = g & 7;
            cpa16(smb + A_OFF + swz(r, c), gA + (size_t)r * 128 + c * 16);
        }
        #pragma unroll
        for (int it = 0; it < 4; ++it) {
            int g = tid + it * 256;
            int r = g >> 3, c = g & 7;
            cpa16(smb + B_OFF + swz(r, c), gB + (size_t)r * 128 + c * 16);
        }
    }
    cp_commit();

    float ssl[8];
    #pragma unroll
    for (int i = 0; i < 8; ++i) ssl[i] = 0.0f;

    for (int t = 0; t < TILES; ++t) {
        const int buf = t & 1;
        if (t + 1 < TILES) {
            const int nb = buf ^ 1;
            const char* gB = (const char*)g_B8 + (size_t)(colbase + (t + 1) * TN) * 128;
            #pragma unroll
            for (int it = 0; it < 4; ++it) {
                int g = tid + it * 256;
                int r = g >> 3, c = g & 7;
                cpa16(smb + B_OFF + nb * 16384 + swz(r, c), gB + (size_t)r * 128 + c * 16);
            }
            cp_commit();
            cp_wait<1>();
        } else {
            cp_wait<0>();
        }
        __syncthreads();

        const uint32_t Ab = smb + A_OFF;
        const uint32_t Bb = smb + B_OFF + buf * 16384;

        #pragma unroll
        for (int half = 0; half < 2; ++half) {
            float c[2][4][4];
            #pragma unroll
            for (int mi = 0; mi < 2; ++mi)
                #pragma unroll
                for (int nj = 0; nj < 4; ++nj)
                    #pragma unroll
                    for (int e = 0; e < 4; ++e) c[mi][nj][e] = 0.0f;

            #pragma unroll
            for (int kk = 0; kk < 4; ++kk) {          // k32 per step, K=128
                const int cs = kk * 2 + (lane >> 4);  // 16B chunk 0..7
                uint32_t af[2][4], bfr[2][4];
                #pragma unroll
                for (int mi = 0; mi < 2; ++mi) {
                    int r = wm * 64 + half * 32 + mi * 16 + (lane & 15);
                    ldsm4(af[mi], Ab + swz(r, cs));
                }
                #pragma unroll
                for (int nb2 = 0; nb2 < 2; ++nb2) {
                    int r = wn * 32 + nb2 * 16 + (lane & 15);
                    ldsm4(bfr[nb2], Bb + swz(r, cs));
                }
                #pragma unroll
                for (int mi = 0; mi < 2; ++mi) {
                    #pragma unroll
                    for (int nb2 = 0; nb2 < 2; ++nb2) {
                        uint32_t b0[2] = { bfr[nb2][0], bfr[nb2][2] };
                        uint32_t b1[2] = { bfr[nb2][1], bfr[nb2][3] };
                        mma16832(c[mi][nb2 * 2 + 0], af[mi], b0);
                        mma16832(c[mi][nb2 * 2 + 1], af[mi], b1);
                    }
                }
            }

            // epilogue: fixed reference M0; pure accumulate
            #pragma unroll
            for (int mi = 0; mi < 2; ++mi) {
                #pragma unroll
                for (int h = 0; h < 2; ++h) {
                    float p = 0.0f;
                    #pragma unroll
                    for (int nj = 0; nj < 4; ++nj) {
                        p += ex2(c[mi][nj][2 * h]     - M0);
                        p += ex2(c[mi][nj][2 * h + 1] - M0);
                    }
                    ssl[half * 4 + mi * 2 + h] += p;
                }
            }
        }
        __syncthreads();   // buf may be overwritten by next iter's prefetch
    }

    // ---- quad sum (4 lanes sharing a row), then combine 4 column-warps ----
    float* rs = (float*)(sm + RED_OFF);      // [4][128]
    #pragma unroll
    for (int slot = 0; slot < 8; ++slot) {
        float s = ssl[slot];
        s += __shfl_xor_sync(0xffffffffu, s, 1);
        s += __shfl_xor_sync(0xffffffffu, s, 2);
        if ((lane & 3) == 0) {
            int row = wm * 64 + (slot >> 2) * 32 + ((slot >> 1) & 1) * 16
                    + (slot & 1) * 8 + (lane >> 2);
            rs[wn * 128 + row] = s;
        }
    }
    __syncthreads();
    if (tid < TM) {
        float S = rs[tid] + rs[128 + tid] + rs[256 + tid] + rs[384 + tid];
        g_ps[blockIdx.y * NT + row0 + tid] = S;
    }
}

// ---------------------------------------------------------------------------
// k_pairs: computes lse2 for its rows from stripe sums, scans all keys once
// per block, recomputes positive dots in fp32 (EXACT t for positive terms),
// accumulates loss; last block finalizes.
// ---------------------------------------------------------------------------
__global__ __launch_bounds__(256)
void k_pairs(const float* __restrict__ logits,
             const float* __restrict__ labels,
             const int*   __restrict__ mask,
             float*       __restrict__ out) {
    __shared__ __align__(16) float qs[GROWS * DD];
    __shared__ long long rkey[GROWS];
    __shared__ float     rlse[GROWS];
    __shared__ int       rval[GROWS];
    __shared__ int       list[LCAP];
    __shared__ int       cnt;

    const int tid = threadIdx.x;
    const int row0 = blockIdx.x * GROWS;

    #pragma unroll
    for (int i = 0; i < GROWS * DD / 256; ++i) {
        int idx = tid + i * 256;
        qs[idx] = logits[row0 * DD + idx];
    }
    if (tid < GROWS) {
        int row = row0 + tid;
        rkey[tid] = g_key[row];
        rval[tid] = mask[row];
        float S = 0.0f;
        #pragma unroll
        for (int st = 0; st < NSTRIPE; ++st) S += g_ps[st * NT + row];
        rlse[tid] = (S > 0.0f) ? (lg2(S) + M0) : NEG_INF;
    }
    if (tid == 0) cnt = 0;
    __syncthreads();

    for (int j = tid; j < NT; j += 256) {
        long long kj = g_key[j];
        #pragma unroll
        for (int r = 0; r < GROWS; ++r) {
            if (rval[r] && kj == rkey[r]) {
                int p = atomicAdd(&cnt, 1);
                if (p < LCAP) {
                    list[p] = r * NT + j;
                } else {
                    float d = 0.0f;
                    for (int k = 0; k < DD; ++k)
                        d += qs[r * DD + k] * labels[j * DD + k];
                    atomicAdd(&g_loss, fminf(rlse[r] - d * LOG2E, CAPV));
                }
            }
        }
    }
    __syncthreads();

    const int count = min(cnt, LCAP);
    const int w = tid >> 5, lane = tid & 31;
    float wsum = 0.0f;
    for (int e = w; e < count; e += 8) {
        int ent = list[e];
        int r = ent >> 13;
        int j = ent & (NT - 1);
        float4 q  = *(const float4*)(qs + r * DD + lane * 4);
        float4 lv = *(const float4*)(labels + j * DD + lane * 4);
        float d = q.x * lv.x + q.y * lv.y + q.z * lv.z + q.w * lv.w;
        d += __shfl_xor_sync(0xffffffffu, d, 16);
        d += __shfl_xor_sync(0xffffffffu, d, 8);
        d += __shfl_xor_sync(0xffffffffu, d, 4);
        d += __shfl_xor_sync(0xffffffffu, d, 2);
        d += __shfl_xor_sync(0xffffffffu, d, 1);
        if (lane == 0) wsum += fminf(rlse[r] - d * LOG2E, CAPV);
    }
    if (lane == 0) atomicAdd(&g_loss, wsum);

    // last block to finish writes the final mean (and resets for graph replay)
    __syncthreads();
    if (tid == 0) {
        __threadfence();
        unsigned prev = atomicAdd(&g_done, 1u);
        if (prev == (unsigned)(gridDim.x - 1)) {
            float total = atomicAdd(&g_loss, 0.0f);  // ordered read
            out[0] = total * (1.0f / (float)NT);
            g_done = 0u;
        }
    }
}

// ---------------------------------------------------------------------------
extern "C" void kernel_launch(void* const* d_in, const int* in_sizes, int n_in,
                              void* d_out, int out_size) {
    const float* logits = (const float*)d_in[0];
    const float* labels = (const float*)d_in[1];
    const int*   mask   = (const int*)d_in[2];
    const void*  ad     = d_in[3];
    (void)in_sizes; (void)n_in; (void)out_size;

    cudaFuncSetAttribute(k_lse_mma, cudaFuncAttributeMaxDynamicSharedMemorySize, SMEM_SZ);

    k_prep<<<1025, 256>>>(logits, labels, ad, mask);
    dim3 grid(NT / TM, NSTRIPE);
    k_lse_mma<<<grid, 256, SMEM_SZ>>>();
    k_pairs<<<NT / GROWS, 256>>>(logits, labels, mask, (float*)d_out);
}